// round 17
// baseline (speedup 1.0000x reference)
#include <cuda_runtime.h>
#include <cuda_bf16.h>
#include <math.h>
#include <stdint.h>

#define NN  100000
#define NE  1600000
#define DD  128
#define NG  64
#define PHH 32
#define NTILES 782   // ceil(NN/128)
#define CAP 128      // bucket capacity per node (Poisson(16): P(>=128) ~ 0)

// ---------------- device scratch (no allocations allowed) ----------------
// INVARIANT: g_cnt, g_gcnt, g_pooled, g_ctr are all-zero at every
// kernel_launch entry; each is re-zeroed after its last reader.
__device__ int      g_cnt[NN];             // in-degree / bucket fill cursor
__device__ int      g_buk[NN * CAP];       // per-node edge buckets (51.2MB)
__device__ int      g_gcnt[NG];
__device__ int      g_ctr;                 // last-block-done counter (mma<1>)
__device__ float    g_norm[NN];
__device__ float    g_pooled[NG * DD];
__device__ uint8_t  g_f8[NN * DD];         // fp8 feature, unscaled (GEMM f0)
__device__ uint8_t  g_fs[NN * DD];         // fp8 norm⊙feature (L1 gather)
__device__ uint8_t  g_xs[NN * DD];         // fp8 norm⊙x1 (L2 gather)
__device__ uint8_t  g_h8[NN * DD];         // fp8 hs (GEMM A operand)
__device__ uint8_t  g_w1h[2][DD * DD];     // eff W1 hi, [n][k], fp8
__device__ uint8_t  g_w1l[2][DD * DD];     // eff W1 lo (residual), fp8
__device__ uint8_t  g_w2h[2][DD * DD];     // eff W2 (x0.5) hi, fp8
__device__ uint8_t  g_w2l[2][DD * DD];     // eff W2 lo (residual), fp8

// ---------------- helpers ----------------
__device__ __forceinline__ uint32_t smem_u32(const void* p) {
    uint32_t a;
    asm("{ .reg .u64 t; cvta.to.shared.u64 t, %1; cvt.u32.u64 %0, t; }"
        : "=r"(a) : "l"(p));
    return a;
}

// pack 2 floats -> e4m3x2 (lo in low byte)
__device__ __forceinline__ uint16_t fp8pack(float lo, float hi) {
    uint16_t r;
    asm("cvt.rn.satfinite.e4m3x2.f32 %0, %1, %2;" : "=h"(r) : "f"(hi), "f"(lo));
    return r;
}

__device__ __forceinline__ uint8_t fp8one(float v) {
    return (uint8_t)(fp8pack(v, 0.f) & 0xFFu);
}

// 4 fp8 (one u32) -> two half2
__device__ __forceinline__ void fp8x4_to_h2x2(uint32_t w, uint32_t& h01, uint32_t& h23) {
    asm("{ .reg .b16 lo, hi;\n\t"
        "mov.b32 {lo, hi}, %2;\n\t"
        "cvt.rn.f16x2.e4m3x2 %0, lo;\n\t"
        "cvt.rn.f16x2.e4m3x2 %1, hi; }"
        : "=r"(h01), "=r"(h23) : "r"(w));
}

__device__ __forceinline__ uint32_t hadd2(uint32_t a, uint32_t b) {
    uint32_t r;
    asm("add.f16x2 %0, %1, %2;" : "=r"(r) : "r"(a), "r"(b));
    return r;
}

__device__ __forceinline__ float2 h2f(uint32_t h) {
    float2 f;
    asm("{ .reg .b16 lo, hi;\n\t"
        "mov.b32 {lo, hi}, %2;\n\t"
        "cvt.f32.f16 %0, lo;\n\t"
        "cvt.f32.f16 %1, hi; }"
        : "=f"(f.x), "=f"(f.y) : "r"(h));
    return f;
}

// fp8 byte -> float (round-trip value of the quantized code)
__device__ __forceinline__ float fp8tof(uint8_t b) {
    uint32_t h01, h23;
    fp8x4_to_h2x2((uint32_t)b, h01, h23);
    return h2f(h01).x;
}

__device__ __forceinline__ void cpa16(uint32_t dst, const void* src) {
    asm volatile("cp.async.cg.shared.global [%0], [%1], 16;"
                 :: "r"(dst), "l"(src) : "memory");
}

__device__ __forceinline__ void ldsm4(uint32_t* r, uint32_t addr) {
    asm volatile("ldmatrix.sync.aligned.m8n8.x4.shared.b16 {%0,%1,%2,%3}, [%4];"
                 : "=r"(r[0]), "=r"(r[1]), "=r"(r[2]), "=r"(r[3]) : "r"(addr));
}

// fp8 e4m3 MMA, K=32 (fragments byte-compatible with bf16 k16 layout)
__device__ __forceinline__ void mma32q(float* c, const uint32_t* a,
                                       uint32_t b0, uint32_t b1) {
    asm volatile(
        "mma.sync.aligned.m16n8k32.row.col.f32.e4m3.e4m3.f32 "
        "{%0,%1,%2,%3}, {%4,%5,%6,%7}, {%8,%9}, {%0,%1,%2,%3};"
        : "+f"(c[0]), "+f"(c[1]), "+f"(c[2]), "+f"(c[3])
        : "r"(a[0]), "r"(a[1]), "r"(a[2]), "r"(a[3]), "r"(b0), "r"(b1));
}

// ---------------- setup ----------------
// fused: bucket CSR fill (single atomic pass) + fp8 feature + hi/lo weights
__global__ void k_fill(const float* __restrict__ feat,
                       const int* __restrict__ src, const int* __restrict__ dst,
                       const float* __restrict__ w11, const float* __restrict__ w21,
                       const float* __restrict__ w12, const float* __restrict__ w22) {
    int i = blockIdx.x * blockDim.x + threadIdx.x;
    if (i < NE) {
        int d = dst[i];
        int p = atomicAdd(&g_cnt[d], 1);
        if (p < CAP) g_buk[(size_t)d * CAP + p] = src[i];
    }
    if (i < NN * DD / 4) {
        float4 v = __ldg((const float4*)feat + i);
        uint16_t p0 = fp8pack(v.x, v.y);
        uint16_t p1 = fp8pack(v.z, v.w);
        ((uint32_t*)g_f8)[i] = (uint32_t)p0 | ((uint32_t)p1 << 16);
    }
    if (i < DD * DD) {
        const float B1 = 0.6931471805599453f;  // log 2
        const float B2 = 0.4054651081081644f;  // log 1.5
        int n = i >> 7, k = i & 127;
        float ikn = (k == n) ? 1.f : 0.f;
        float W;
        uint8_t hi;
        W = B1 * w11[k * DD + n] + (1.f - B1) * ikn;
        hi = fp8one(W);
        g_w1h[0][i] = hi; g_w1l[0][i] = fp8one(W - fp8tof(hi));
        W = 0.5f * (B1 * w21[k * DD + n] + (1.f - B1) * ikn);
        hi = fp8one(W);
        g_w2h[0][i] = hi; g_w2l[0][i] = fp8one(W - fp8tof(hi));
        W = B2 * w12[k * DD + n] + (1.f - B2) * ikn;
        hi = fp8one(W);
        g_w1h[1][i] = hi; g_w1l[1][i] = fp8one(W - fp8tof(hi));
        W = 0.5f * (B2 * w22[k * DD + n] + (1.f - B2) * ikn);
        hi = fp8one(W);
        g_w2h[1][i] = hi; g_w2l[1][i] = fp8one(W - fp8tof(hi));
    }
}

// norm + gcnt + fp8 norm⊙feature (one u32 word = 4 fp8 per thread)
__global__ void k_scale(const int* __restrict__ gids) {
    int i = blockIdx.x * blockDim.x + threadIdx.x;
    if (i < NN * DD / 4) {
        int node = i >> 5;
        float nrm = rsqrtf((float)(g_cnt[node] + 1));   // +1 self loop
        if ((i & 31) == 0) {
            g_norm[node] = nrm;
            atomicAdd(&g_gcnt[gids[node]], 1);
        }
        uint32_t q = ((const uint32_t*)g_f8)[i];
        uint32_t h01, h23;
        fp8x4_to_h2x2(q, h01, h23);
        float2 a = h2f(h01), b = h2f(h23);
        uint16_t p0 = fp8pack(a.x * nrm, a.y * nrm);
        uint16_t p1 = fp8pack(b.x * nrm, b.y * nrm);
        ((uint32_t*)g_fs)[i] = (uint32_t)p0 | ((uint32_t)p1 << 16);
    }
}

// ---- SpMM (fp8 gather, half2 accumulate): hs_fp8 = 0.5*nrm*(x̃[n]+Σx̃[src])
// 16-lane node groups (uint2 = 8 fp8/lane), 8-edge unroll, bucket CSR.
__global__ void k_spmm(const uint8_t* __restrict__ fin, uint8_t* __restrict__ fout) {
    int gt = blockIdx.x * blockDim.x + threadIdx.x;
    int node = gt >> 4, lane = gt & 15;
    if (node >= NN) return;
    const uint2* F = (const uint2*)fin;     // row = 128B = 16 x uint2
    uint2 a = __ldg(F + (size_t)node * 16 + lane);   // self loop (pre-scaled)
    uint32_t h[4];
    fp8x4_to_h2x2(a.x, h[0], h[1]);
    fp8x4_to_h2x2(a.y, h[2], h[3]);

    const int* buk = g_buk + (size_t)node * CAP;
    int cnt = g_cnt[node];
    if (cnt > CAP) cnt = CAP;
    int e = 0;
    for (; e + 8 <= cnt; e += 8) {
        uint2 v[8];
        #pragma unroll
        for (int j = 0; j < 8; j++) {
            int s = __ldg(buk + e + j);
            v[j] = __ldg(F + (size_t)s * 16 + lane);
        }
        #pragma unroll
        for (int j = 0; j < 8; j++) {
            uint32_t c0, c1, c2, c3;
            fp8x4_to_h2x2(v[j].x, c0, c1);
            fp8x4_to_h2x2(v[j].y, c2, c3);
            h[0] = hadd2(h[0], c0);
            h[1] = hadd2(h[1], c1);
            h[2] = hadd2(h[2], c2);
            h[3] = hadd2(h[3], c3);
        }
    }
    for (; e < cnt; e++) {
        int s = __ldg(buk + e);
        uint2 v0 = __ldg(F + (size_t)s * 16 + lane);
        uint32_t c0, c1, c2, c3;
        fp8x4_to_h2x2(v0.x, c0, c1);
        fp8x4_to_h2x2(v0.y, c2, c3);
        h[0] = hadd2(h[0], c0);
        h[1] = hadd2(h[1], c1);
        h[2] = hadd2(h[2], c2);
        h[3] = hadd2(h[3], c3);
    }
    float sc = 0.5f * g_norm[node];
    float2 f0 = h2f(h[0]), f1 = h2f(h[1]), f2 = h2f(h[2]), f3 = h2f(h[3]);
    uint16_t p0 = fp8pack(f0.x * sc, f0.y * sc);
    uint16_t p1 = fp8pack(f1.x * sc, f1.y * sc);
    uint16_t p2 = fp8pack(f2.x * sc, f2.y * sc);
    uint16_t p3 = fp8pack(f3.x * sc, f3.y * sc);
    uint2 o;
    o.x = (uint32_t)p0 | ((uint32_t)p1 << 16);
    o.y = (uint32_t)p2 | ((uint32_t)p3 << 16);
    ((uint2*)fout)[(size_t)node * 16 + lane] = o;
}

// ---- fp8 mma.sync GEMM with hi/lo weights: relu(hs@W1e + f0@W2e + b) ------
// BM=128, BN=128, K=256 (hs|f0), 2 chunks of K=128 fp8; per chunk the B
// operand is split hi+lo (error-compensated fp8) -> 2x MMAs, shared fp32 acc.
// MODE 0: write fp8 norm⊙x1. MODE 1: pool; last block runs decoder MLP;
//         re-zeros g_cnt.
template <int MODE>
__global__ void __launch_bounds__(256, 2)
k_mma(const uint8_t* __restrict__ Ahs, const uint8_t* __restrict__ Af0,
      const uint8_t* __restrict__ Bw1h, const uint8_t* __restrict__ Bw1l,
      const uint8_t* __restrict__ Bw2h, const uint8_t* __restrict__ Bw2l,
      const float* __restrict__ bias, uint8_t* __restrict__ x8out,
      const int* __restrict__ gids,
      const float* __restrict__ d1w, const float* __restrict__ d1b,
      const float* __restrict__ d2w, const float* __restrict__ d2b,
      float* __restrict__ out) {
    extern __shared__ float smem[];   // 2 chunks x (A 16KB + Bh 16KB + Bl 16KB)
    uint32_t sb = smem_u32(smem);
    int t = threadIdx.x, lane = t & 31, w = t >> 5;
    int wm = (w & 3) * 32, wn = (w >> 2) * 64;
    int R0 = blockIdx.x * 128;

    float acc[2][8][4];
    #pragma unroll
    for (int mt = 0; mt < 2; mt++)
        #pragma unroll
        for (int j = 0; j < 8; j++)
            #pragma unroll
            for (int q = 0; q < 4; q++) acc[mt][j][q] = 0.f;

    auto load_chunk = [&](int c) {
        uint32_t base = sb + (uint32_t)c * 49152u;
        const uint8_t* A  = c ? Af0 : Ahs;
        const uint8_t* Bh = c ? Bw2h : Bw1h;
        const uint8_t* Bl = c ? Bw2l : Bw1l;
        #pragma unroll
        for (int i = 0; i < 4; i++) {
            int idx = i * 256 + t;
            int r = idx >> 3, f4 = idx & 7;
            int row = R0 + r; if (row >= NN) row = 0;
            uint32_t off = r * 128 + ((f4 * 16) ^ ((r & 7) << 4));
            cpa16(base + off,          A  + (size_t)row * DD + f4 * 16);
            cpa16(base + 16384u + off, Bh + (size_t)r * DD + f4 * 16);
            cpa16(base + 32768u + off, Bl + (size_t)r * DD + f4 * 16);
        }
        asm volatile("cp.async.commit_group;" ::: "memory");
    };

    load_chunk(0);
    load_chunk(1);

    int rA[2], rB[4];
    #pragma unroll
    for (int mt = 0; mt < 2; mt++)
        rA[mt] = wm + mt * 16 + (lane & 7) + ((lane >> 3) & 1) * 8;
    #pragma unroll
    for (int nt = 0; nt < 4; nt++)
        rB[nt] = wn + nt * 16 + (lane & 7) + ((lane >> 4) & 1) * 8;
    uint32_t aH = ((lane >> 4) & 1) * 16;
    uint32_t bH = ((lane >> 3) & 1) * 16;

    #pragma unroll
    for (int c = 0; c < 2; c++) {
        if (c == 0) asm volatile("cp.async.wait_group 1;" ::: "memory");
        else        asm volatile("cp.async.wait_group 0;" ::: "memory");
        __syncthreads();

        uint32_t aB  = sb + (uint32_t)c * 49152u;
        uint32_t bBh = aB + 16384u;
        uint32_t bBl = aB + 32768u;
        #pragma unroll
        for (int kk = 0; kk < 4; kk++) {   // k32 per step, 4 steps = K 128 fp8
            uint32_t a[2][4], b[4][4];
            #pragma unroll
            for (int mt = 0; mt < 2; mt++)
                ldsm4(a[mt], aB + rA[mt] * 128 +
                              (((uint32_t)(kk * 32) + aH) ^ ((rA[mt] & 7) << 4)));
            // hi weights
            #pragma unroll
            for (int nt = 0; nt < 4; nt++)
                ldsm4(b[nt], bBh + rB[nt] * 128 +
                              (((uint32_t)(kk * 32) + bH) ^ ((rB[nt] & 7) << 4)));
            #pragma unroll
            for (int mt = 0; mt < 2; mt++)
                #pragma unroll
                for (int nt = 0; nt < 4; nt++) {
                    mma32q(acc[mt][2 * nt + 0], a[mt], b[nt][0], b[nt][1]);
                    mma32q(acc[mt][2 * nt + 1], a[mt], b[nt][2], b[nt][3]);
                }
            // lo (residual) weights
            #pragma unroll
            for (int nt = 0; nt < 4; nt++)
                ldsm4(b[nt], bBl + rB[nt] * 128 +
                              (((uint32_t)(kk * 32) + bH) ^ ((rB[nt] & 7) << 4)));
            #pragma unroll
            for (int mt = 0; mt < 2; mt++)
                #pragma unroll
                for (int nt = 0; nt < 4; nt++) {
                    mma32q(acc[mt][2 * nt + 0], a[mt], b[nt][0], b[nt][1]);
                    mma32q(acc[mt][2 * nt + 1], a[mt], b[nt][2], b[nt][3]);
                }
        }
    }

    if (MODE == 0) {
        // epilogue: bias + relu + norm-prescale + fp8 pack
        #pragma unroll
        for (int mt = 0; mt < 2; mt++) {
            int row0 = R0 + wm + mt * 16 + (lane >> 2);
            float nr0 = (row0 < NN) ? g_norm[row0] : 0.f;
            float nr1 = (row0 + 8 < NN) ? g_norm[row0 + 8] : 0.f;
            #pragma unroll
            for (int j = 0; j < 8; j++) {
                int col = wn + j * 8 + (lane & 3) * 2;
                float2 bb = *(const float2*)(bias + col);
                float v0 = fmaxf(acc[mt][j][0] + bb.x, 0.f) * nr0;
                float v1 = fmaxf(acc[mt][j][1] + bb.y, 0.f) * nr0;
                float v2 = fmaxf(acc[mt][j][2] + bb.x, 0.f) * nr1;
                float v3 = fmaxf(acc[mt][j][3] + bb.y, 0.f) * nr1;
                if (row0 < NN)
                    *(uint16_t*)(x8out + (size_t)row0 * DD + col) = fp8pack(v0, v1);
                if (row0 + 8 < NN)
                    *(uint16_t*)(x8out + (size_t)(row0 + 8) * DD + col) = fp8pack(v2, v3);
            }
        }
    } else {
        // pooled epilogue: rows r0, r0+8, r0+16, r0+24 per thread
        int r0 = R0 + wm + (lane >> 2);
        int ra = r0, rb = r0 + 8, rc = r0 + 16, rd = r0 + 24;
        bool va = ra < NN, vb = rb < NN, vc = rc < NN, vd = rd < NN;
        // re-zero g_cnt (last reader was spmm L2); one writer per row
        if ((lane & 3) == 0 && wn == 0) {
            if (va) g_cnt[ra] = 0;
            if (vb) g_cnt[rb] = 0;
            if (vc) g_cnt[rc] = 0;
            if (vd) g_cnt[rd] = 0;
        }
        if (va) {
            int ga = __ldg(gids + ra);
            int gb = vb ? __ldg(gids + rb) : ga;
            int gc = vc ? __ldg(gids + rc) : ga;
            int gd = vd ? __ldg(gids + rd) : ga;
            bool same = (ga == gb) && (gb == gc) && (gc == gd);
            #pragma unroll
            for (int j = 0; j < 8; j++) {
                int col = wn + j * 8 + (lane & 3) * 2;
                float2 bb = *(const float2*)(bias + col);
                #pragma unroll
                for (int q = 0; q < 2; q++) {
                    float bq = q ? bb.y : bb.x;
                    float u0 = va ? fmaxf(acc[0][j][q + 0] + bq, 0.f) : 0.f;
                    float u1 = vb ? fmaxf(acc[0][j][q + 2] + bq, 0.f) : 0.f;
                    float u2 = vc ? fmaxf(acc[1][j][q + 0] + bq, 0.f) : 0.f;
                    float u3 = vd ? fmaxf(acc[1][j][q + 2] + bq, 0.f) : 0.f;
                    if (same) {
                        atomicAdd(&g_pooled[ga * DD + col + q], u0 + u1 + u2 + u3);
                    } else {
                        atomicAdd(&g_pooled[ga * DD + col + q], u0);
                        if (vb) atomicAdd(&g_pooled[gb * DD + col + q], u1);
                        if (vc) atomicAdd(&g_pooled[gc * DD + col + q], u2);
                        if (vd) atomicAdd(&g_pooled[gd * DD + col + q], u3);
                    }
                }
            }
        }

        // ---- last-block-done: run the decoder MLP inline ----
        __shared__ int is_last;
        __threadfence();
        __syncthreads();
        if (t == 0) {
            int v = atomicAdd(&g_ctr, 1);
            is_last = (v == NTILES - 1);
            if (is_last) g_ctr = 0;          // restore zero for next replay
        }
        __syncthreads();
        if (is_last) {
            __threadfence();                 // see all blocks' pooled atomics
            int b = t;
            if (b < NG) {
                float inv = 1.f / fmaxf((float)g_gcnt[b], 1.f);
                float h[PHH];
                #pragma unroll
                for (int p = 0; p < PHH; p++) h[p] = __ldg(d1b + p);
                for (int c2 = 0; c2 < DD; c2++) {
                    float a2 = g_pooled[b * DD + c2] * inv;
                    g_pooled[b * DD + c2] = 0.f;   // restore zero
                    #pragma unroll
                    for (int p = 0; p < PHH; p++)
                        h[p] = fmaf(a2, __ldg(d1w + c2 * PHH + p), h[p]);
                }
                g_gcnt[b] = 0;                     // restore zero
                float z = __ldg(d2b);
                #pragma unroll
                for (int p = 0; p < PHH; p++)
                    z = fmaf(fmaxf(h[p], 0.f), __ldg(d2w + p), z);
                out[b] = 1.f / (1.f + expf(-z));
            }
        }
    }
}

// ---------------- launch ----------------
extern "C" void kernel_launch(void* const* d_in, const int* in_sizes, int n_in,
                              void* d_out, int out_size) {
    const float* feature = (const float*)d_in[0];
    const int*   src     = (const int*)d_in[1];
    const int*   dst     = (const int*)d_in[2];
    const int*   gids    = (const int*)d_in[3];
    const float* w1_1    = (const float*)d_in[4];
    const float* w2_1    = (const float*)d_in[5];
    const float* b_1     = (const float*)d_in[6];
    const float* w1_2    = (const float*)d_in[7];
    const float* w2_2    = (const float*)d_in[8];
    const float* b_2     = (const float*)d_in[9];
    const float* d1w     = (const float*)d_in[10];
    const float* d1b     = (const float*)d_in[11];
    const float* d2w     = (const float*)d_in[12];
    const float* d2b     = (const float*)d_in[13];
    float* out = (float*)d_out;

    uint8_t *f8_p = nullptr, *fs_p = nullptr, *xs_p = nullptr, *h8_p = nullptr;
    uint8_t *w1h_p = nullptr, *w1l_p = nullptr, *w2h_p = nullptr, *w2l_p = nullptr;
    cudaGetSymbolAddress((void**)&f8_p,   g_f8);
    cudaGetSymbolAddress((void**)&fs_p,   g_fs);
    cudaGetSymbolAddress((void**)&xs_p,   g_xs);
    cudaGetSymbolAddress((void**)&h8_p,   g_h8);
    cudaGetSymbolAddress((void**)&w1h_p,  g_w1h);
    cudaGetSymbolAddress((void**)&w1l_p,  g_w1l);
    cudaGetSymbolAddress((void**)&w2h_p,  g_w2h);
    cudaGetSymbolAddress((void**)&w2l_p,  g_w2l);

    const int SMEM_MMA = 98304;   // 2 chunks x (A 16KB + Bh 16KB + Bl 16KB)
    cudaFuncSetAttribute(k_mma<0>, cudaFuncAttributeMaxDynamicSharedMemorySize, SMEM_MMA);
    cudaFuncSetAttribute(k_mma<1>, cudaFuncAttributeMaxDynamicSharedMemorySize, SMEM_MMA);

    k_fill<<<(NN * DD / 4 + 255) / 256, 256>>>(feature, src, dst,
                                               w1_1, w2_1, w1_2, w2_2);
    k_scale<<<(NN * DD / 4 + 255) / 256, 256>>>(gids);

    // layer 1: spmm gathers fp8 norm⊙feature -> hs (fp8);
    //          gemm (h8, f8) -> fp8 norm⊙x1
    k_spmm<<<(NN * 16 + 255) / 256, 256>>>(fs_p, h8_p);
    k_mma<0><<<NTILES, 256, SMEM_MMA>>>(h8_p, f8_p, w1h_p, w1l_p, w2h_p, w2l_p,
                                        b_1, xs_p, gids,
                                        nullptr, nullptr, nullptr, nullptr, nullptr);
    // layer 2: spmm gathers fp8 norm⊙x1 -> hs (fp8);
    //          gemm (h8, f8) pools into g_pooled; last block runs decoder MLP
    k_spmm<<<(NN * 16 + 255) / 256, 256>>>(xs_p, h8_p);
    k_mma<1><<<NTILES, 256, SMEM_MMA>>>(h8_p, f8_p,
                                        w1h_p + DD * DD, w1l_p + DD * DD,
                                        w2h_p + DD * DD, w2l_p + DD * DD,
                                        b_2, nullptr, gids, d1w, d1b, d2w, d2b, out);
}